// round 14
// baseline (speedup 1.0000x reference)
#include <cuda_runtime.h>
#include <math.h>
#include <stdint.h>

#define N_NODES 50000
#define N_EDGES 800000
#define NF 64
#define TILE_E 64
#define N_TILES (N_EDGES / TILE_E)   // 12500 edge tiles
#define N_NTILES (N_NODES / 16)      // 3125 node tiles
#define GRID_NODE 296                // 2 CTAs/SM resident (smem ~76KB)
#define GRID_EDGE 296                // 2 CTAs/SM (smem ~98KB)

#define SWR_STRIDE 200               // 32 x 200 tf32 bits (bank conflict-free)
#define SRAD_STRIDE 36               // 64 x 36 raw fp32 (16B-aligned rows, cf-free)
#define SW_STRIDE 200                // 64 x 200 f32 W tile
#define SW2_STRIDE 200               // 64 x 200 tf32 W2
#define SH_STRIDE 68                 // 16 x 68 tf32 h

__device__ __align__(16) float g_phi[N_NODES * 3 * NF];    // 38.4 MB

__device__ __forceinline__ uint32_t f2tf32(float f) {
    uint32_t r;
    asm("cvt.rna.tf32.f32 %0, %1;" : "=r"(r) : "f"(f));
    return r;
}

__device__ __forceinline__ void mma_tf32(float c[4], const uint32_t a[4],
                                         uint32_t b0, uint32_t b1) {
    asm("mma.sync.aligned.m16n8k8.row.col.f32.tf32.tf32.f32 "
        "{%0,%1,%2,%3}, {%4,%5,%6,%7}, {%8,%9}, {%0,%1,%2,%3};"
        : "+f"(c[0]), "+f"(c[1]), "+f"(c[2]), "+f"(c[3])
        : "r"(a[0]), "r"(a[1]), "r"(a[2]), "r"(a[3]), "r"(b0), "r"(b1));
}

__device__ __forceinline__ void red_add_v4(float* p, float a, float b, float c, float d) {
    asm volatile("red.global.add.v4.f32 [%0], {%1, %2, %3, %4};"
                 :: "l"(p), "f"(a), "f"(b), "f"(c), "f"(d));
}

__device__ __forceinline__ void cp_async16(void* smem, const void* gmem) {
    uint32_t sa = (uint32_t)__cvta_generic_to_shared(smem);
    asm volatile("cp.async.cg.shared.global [%0], [%1], 16;" :: "r"(sa), "l"(gmem));
}
#define CP_COMMIT() asm volatile("cp.async.commit_group;" ::: "memory")
#define CP_WAIT1()  asm volatile("cp.async.wait_group 1;" ::: "memory")

// ---------- Persistent node kernel: out=[s|v] copy + phi MLP (tf32 mma) ----------
__global__ void __launch_bounds__(256) k_node(
    const float* __restrict__ s, const float* __restrict__ v,
    const float* __restrict__ W1, const float* __restrict__ b1,
    const float* __restrict__ W2, const float* __restrict__ b2,
    float* __restrict__ out) {
    __shared__ float sW1[NF * NF];            // 16 KB
    __shared__ uint32_t sW2T[NF * SW2_STRIDE]; // 51.2 KB tf32
    __shared__ float sS[16 * NF];             // 4 KB
    __shared__ uint32_t sHT[16 * SH_STRIDE];  // 4.35 KB tf32

    int tid = threadIdx.x;

    // out = [s | v] (grid-stride; overlaps weight staging + MLP)
    {
        const int NS4 = N_NODES * NF / 4;
        const int NV4 = N_NODES * 3 * NF / 4;
        const float4* s4 = (const float4*)s;
        const float4* v4 = (const float4*)v;
        float4* out4 = (float4*)out;
        for (int i = blockIdx.x * 256 + tid; i < NS4 + NV4; i += GRID_NODE * 256) {
            if (i < NS4) out4[i] = s4[i];
            else out4[i] = v4[i - NS4];
        }
    }

    for (int i = tid; i < NF * NF; i += 256) sW1[i] = W1[i];
    for (int i = tid; i < NF * 192; i += 256) {
        int k = i / 192, n = i % 192;
        sW2T[k * SW2_STRIDE + n] = f2tf32(W2[i]);
    }

    int c = tid & 63;
    int q = tid >> 6;
    float bb1 = b1[c];

    // phase-2 mma mapping: 8 warps x n24 each (3 n-tiles), m16, k64 (8 ksteps)
    int wid = tid >> 5, lane = tid & 31;
    int kc = lane & 3;
    int mr = lane >> 2;
    float2 bias[3];
#pragma unroll
    for (int nt = 0; nt < 3; nt++)
        bias[nt] = *(const float2*)&b2[wid * 24 + nt * 8 + (lane & 3) * 2];

    for (int tile = blockIdx.x; tile < N_NTILES; tile += GRID_NODE) {
        int node0 = tile * 16;
        __syncthreads();
        for (int i = tid; i < 16 * NF; i += 256) sS[i] = s[node0 * NF + i];
        __syncthreads();

        // Phase 1: h = silu(s @ W1 + b1) -> sHT (tf32 bits)
        {
            float a0 = bb1, a1 = bb1, a2 = bb1, a3 = bb1;
            const float* sr = &sS[q * 4 * NF];
#pragma unroll 8
            for (int k = 0; k < NF; k++) {
                float w = sW1[k * NF + c];
                a0 += sr[k] * w;
                a1 += sr[NF + k] * w;
                a2 += sr[2 * NF + k] * w;
                a3 += sr[3 * NF + k] * w;
            }
            int o = q * 4;
            sHT[o * SH_STRIDE + c]       = f2tf32(a0 / (1.f + expf(-a0)));
            sHT[(o + 1) * SH_STRIDE + c] = f2tf32(a1 / (1.f + expf(-a1)));
            sHT[(o + 2) * SH_STRIDE + c] = f2tf32(a2 / (1.f + expf(-a2)));
            sHT[(o + 3) * SH_STRIDE + c] = f2tf32(a3 / (1.f + expf(-a3)));
        }
        __syncthreads();

        // Phase 2: phi = h @ W2 + b2 via tf32 mma (m16 x n24 per warp)
        float C[3][4];
#pragma unroll
        for (int nt = 0; nt < 3; nt++) {
            C[nt][0] = bias[nt].x; C[nt][1] = bias[nt].y;
            C[nt][2] = bias[nt].x; C[nt][3] = bias[nt].y;
        }
#pragma unroll
        for (int ks = 0; ks < 8; ks++) {
            uint32_t a[4];
            int col = ks * 8 + kc;
            a[0] = sHT[mr * SH_STRIDE + col];
            a[1] = sHT[(mr + 8) * SH_STRIDE + col];
            a[2] = sHT[mr * SH_STRIDE + col + 4];
            a[3] = sHT[(mr + 8) * SH_STRIDE + col + 4];
#pragma unroll
            for (int nt = 0; nt < 3; nt++) {
                int ncol = wid * 24 + nt * 8 + mr;
                uint32_t b0 = sW2T[(ks * 8 + kc) * SW2_STRIDE + ncol];
                uint32_t b1 = sW2T[(ks * 8 + kc + 4) * SW2_STRIDE + ncol];
                mma_tf32(C[nt], a, b0, b1);
            }
        }
#pragma unroll
        for (int nt = 0; nt < 3; nt++) {
            int col = wid * 24 + nt * 8 + (lane & 3) * 2;
            *(float2*)&g_phi[(node0 + mr) * 192 + col] = make_float2(C[nt][0], C[nt][1]);
            *(float2*)&g_phi[(node0 + mr + 8) * 192 + col] = make_float2(C[nt][2], C[nt][3]);
        }
    }
}

// ---------- Persistent edge kernel: cp.async double-buffered tiles ----------
__global__ void __launch_bounds__(256) k_edge(
    const float* __restrict__ v, const float* __restrict__ radial,
    const float* __restrict__ f_cut, const float* __restrict__ uvec,
    const int* __restrict__ eidx, const float* __restrict__ Wr,
    const float* __restrict__ br, float* __restrict__ out) {
    __shared__ uint32_t sWrT[32 * SWR_STRIDE];                       // 25.6 KB
    __shared__ __align__(16) float sRad[2][TILE_E * SRAD_STRIDE];    // 2 x 9.2 KB
    __shared__ __align__(16) float sW[TILE_E * SW_STRIDE];           // 51.2 KB
    __shared__ __align__(16) int sIJ[2][2 * TILE_E];                 // 2 x 512 B
    __shared__ __align__(16) float sFc[2][TILE_E];                   // 2 x 256 B
    __shared__ __align__(16) float sU[2][TILE_E * 3];                // 2 x 768 B

    int tid = threadIdx.x;

    for (int i = tid; i < 32 * 192; i += 256) {
        int r = i / 192, c = i % 192;
        sWrT[r * SWR_STRIDE + c] = f2tf32(Wr[i]);
    }

    // GEMM mapping: 8 warps = 4 m-tiles x 2 n-halves (m16 x n96 each)
    int wid = tid >> 5, lane = tid & 31;
    int mt = wid & 3;
    int nh = wid >> 2;
    int rlo = mt * 16 + (lane >> 2);
    int kc = lane & 3;
    int nb = nh * 96 + (lane >> 2);

    // Epilogue mapping
    int g = tid & 15;
    int eq = tid >> 4;
    float4 Bs = *(const float4*)&br[4 * g];
    float4 Bv = *(const float4*)&br[NF + 4 * g];
    float4 Bx = *(const float4*)&br[2 * NF + 4 * g];

    // tile-fill via cp.async: rad (512 x 16B) + meta (96 x 16B)
    auto issue_tile = [&](int t, int b) {
        // rad: 64 rows x 128B; thread handles 2 chunks
        for (int i = tid; i < 512; i += 256) {
            int e = i >> 3, c = i & 7;
            cp_async16(&sRad[b][e * SRAD_STRIDE + c * 4],
                       radial + (size_t)t * TILE_E * 32 + e * 32 + c * 4);
        }
        if (tid < 16)
            cp_async16(&sIJ[b][tid * 4], eidx + t * TILE_E + tid * 4);
        else if (tid < 32)
            cp_async16(&sIJ[b][64 + (tid - 16) * 4],
                       eidx + N_EDGES + t * TILE_E + (tid - 16) * 4);
        else if (tid < 48)
            cp_async16(&sFc[b][(tid - 32) * 4], f_cut + t * TILE_E + (tid - 32) * 4);
        else if (tid < 96)
            cp_async16(&sU[b][(tid - 48) * 4],
                       uvec + (size_t)t * TILE_E * 3 + (tid - 48) * 4);
    };

    int cb = 0;
    issue_tile(blockIdx.x, 0);
    CP_COMMIT();

    for (int tile = blockIdx.x; tile < N_TILES; tile += GRID_EDGE) {
        int tn = tile + GRID_EDGE;
        if (tn >= N_TILES) tn = tile;          // clamped dummy prefetch (uniform groups)
        issue_tile(tn, cb ^ 1);
        CP_COMMIT();
        CP_WAIT1();                             // buf[cb] complete
        __syncthreads();                        // publish buf[cb]

        // ---- tf32 GEMM: W' = rad @ Wr  (64x32 @ 32x192) ----
        uint32_t a[4][4];
#pragma unroll
        for (int ks = 0; ks < 4; ks++) {
            int col = ks * 8 + kc;
            a[ks][0] = f2tf32(sRad[cb][rlo * SRAD_STRIDE + col]);
            a[ks][1] = f2tf32(sRad[cb][(rlo + 8) * SRAD_STRIDE + col]);
            a[ks][2] = f2tf32(sRad[cb][rlo * SRAD_STRIDE + col + 4]);
            a[ks][3] = f2tf32(sRad[cb][(rlo + 8) * SRAD_STRIDE + col + 4]);
        }

        float c[12][4];
#pragma unroll
        for (int nt = 0; nt < 12; nt++) {
            c[nt][0] = 0.f; c[nt][1] = 0.f; c[nt][2] = 0.f; c[nt][3] = 0.f;
            int ncol = nb + nt * 8;
#pragma unroll
            for (int ks = 0; ks < 4; ks++) {
                uint32_t b0 = sWrT[(ks * 8 + kc) * SWR_STRIDE + ncol];
                uint32_t b1 = sWrT[(ks * 8 + kc + 4) * SWR_STRIDE + ncol];
                mma_tf32(c[nt], a[ks], b0, b1);
            }
        }

#pragma unroll
        for (int nt = 0; nt < 12; nt++) {
            int col = nh * 96 + nt * 8 + (lane & 3) * 2;
            *(float2*)&sW[rlo * SW_STRIDE + col] = make_float2(c[nt][0], c[nt][1]);
            *(float2*)&sW[(rlo + 8) * SW_STRIDE + col] = make_float2(c[nt][2], c[nt][3]);
        }
        __syncthreads();

        // ---- epilogue: 2-edge prefetch batches (R11 structure) ----
        const int* sIc = sIJ[cb];
        const int* sJc = sIJ[cb] + 64;
        const float* sFcc = sFc[cb];
        const float* sUc = sU[cb];
#pragma unroll
        for (int half = 0; half < 2; half++) {
            int elA = eq * 4 + half * 2;
            int elB = elA + 1;
            int iA = sIc[elA], jA = sJc[elA];
            int iB = sIc[elB], jB = sJc[elB];
            float fcA = sFcc[elA], fcB = sFcc[elB];

            const float4* pjA = (const float4*)&g_phi[jA * 192 + 4 * g];
            const float4* vjA = (const float4*)&v[(size_t)jA * 192 + 4 * g];
            const float4* pjB = (const float4*)&g_phi[jB * 192 + 4 * g];
            const float4* vjB = (const float4*)&v[(size_t)jB * 192 + 4 * g];
            float4 psA = pjA[0], pvA = pjA[16], pxA = pjA[32];
            float4 vdA0 = vjA[0], vdA1 = vjA[16], vdA2 = vjA[32];
            float4 psB = pjB[0], pvB = pjB[16], pxB = pjB[32];
            float4 vdB0 = vjB[0], vdB1 = vjB[16], vdB2 = vjB[32];

            {
                const float* wrow = &sW[elA * SW_STRIDE + 4 * g];
                float4 wsv = *(const float4*)wrow;
                float4 wvv = *(const float4*)(wrow + 64);
                float4 wxv = *(const float4*)(wrow + 128);

                float xs0 = psA.x * ((wsv.x + Bs.x) * fcA), xs1 = psA.y * ((wsv.y + Bs.y) * fcA);
                float xs2 = psA.z * ((wsv.z + Bs.z) * fcA), xs3 = psA.w * ((wsv.w + Bs.w) * fcA);
                red_add_v4(out + iA * NF + 4 * g, xs0, xs1, xs2, xs3);

                float xvv0 = pvA.x * ((wvv.x + Bv.x) * fcA), xvv1 = pvA.y * ((wvv.y + Bv.y) * fcA);
                float xvv2 = pvA.z * ((wvv.z + Bv.z) * fcA), xvv3 = pvA.w * ((wvv.w + Bv.w) * fcA);
                float xvs0 = pxA.x * ((wxv.x + Bx.x) * fcA), xvs1 = pxA.y * ((wxv.y + Bx.y) * fcA);
                float xvs2 = pxA.z * ((wxv.z + Bx.z) * fcA), xvs3 = pxA.w * ((wxv.w + Bx.w) * fcA);

                float u0 = sUc[elA * 3 + 0], u1 = sUc[elA * 3 + 1], u2 = sUc[elA * 3 + 2];
                float* ov = out + N_NODES * NF + iA * 192 + 4 * g;
                red_add_v4(ov,
                           vdA0.x * xvv0 + xvs0 * u0, vdA0.y * xvv1 + xvs1 * u0,
                           vdA0.z * xvv2 + xvs2 * u0, vdA0.w * xvv3 + xvs3 * u0);
                red_add_v4(ov + 64,
                           vdA1.x * xvv0 + xvs0 * u1, vdA1.y * xvv1 + xvs1 * u1,
                           vdA1.z * xvv2 + xvs2 * u1, vdA1.w * xvv3 + xvs3 * u1);
                red_add_v4(ov + 128,
                           vdA2.x * xvv0 + xvs0 * u2, vdA2.y * xvv1 + xvs1 * u2,
                           vdA2.z * xvv2 + xvs2 * u2, vdA2.w * xvv3 + xvs3 * u2);
            }
            {
                const float* wrow = &sW[elB * SW_STRIDE + 4 * g];
                float4 wsv = *(const float4*)wrow;
                float4 wvv = *(const float4*)(wrow + 64);
                float4 wxv = *(const float4*)(wrow + 128);

                float xs0 = psB.x * ((wsv.x + Bs.x) * fcB), xs1 = psB.y * ((wsv.y + Bs.y) * fcB);
                float xs2 = psB.z * ((wsv.z + Bs.z) * fcB), xs3 = psB.w * ((wsv.w + Bs.w) * fcB);
                red_add_v4(out + iB * NF + 4 * g, xs0, xs1, xs2, xs3);

                float xvv0 = pvB.x * ((wvv.x + Bv.x) * fcB), xvv1 = pvB.y * ((wvv.y + Bv.y) * fcB);
                float xvv2 = pvB.z * ((wvv.z + Bv.z) * fcB), xvv3 = pvB.w * ((wvv.w + Bv.w) * fcB);
                float xvs0 = pxB.x * ((wxv.x + Bx.x) * fcB), xvs1 = pxB.y * ((wxv.y + Bx.y) * fcB);
                float xvs2 = pxB.z * ((wxv.z + Bx.z) * fcB), xvs3 = pxB.w * ((wxv.w + Bx.w) * fcB);

                float u0 = sUc[elB * 3 + 0], u1 = sUc[elB * 3 + 1], u2 = sUc[elB * 3 + 2];
                float* ov = out + N_NODES * NF + iB * 192 + 4 * g;
                red_add_v4(ov,
                           vdB0.x * xvv0 + xvs0 * u0, vdB0.y * xvv1 + xvs1 * u0,
                           vdB0.z * xvv2 + xvs2 * u0, vdB0.w * xvv3 + xvs3 * u0);
                red_add_v4(ov + 64,
                           vdB1.x * xvv0 + xvs0 * u1, vdB1.y * xvv1 + xvs1 * u1,
                           vdB1.z * xvv2 + xvs2 * u1, vdB1.w * xvv3 + xvs3 * u1);
                red_add_v4(ov + 128,
                           vdB2.x * xvv0 + xvs0 * u2, vdB2.y * xvv1 + xvs1 * u2,
                           vdB2.z * xvv2 + xvs2 * u2, vdB2.w * xvv3 + xvs3 * u2);
            }
        }
        __syncthreads();   // all reads of buf[cb] + sW done before next overwrite
        cb ^= 1;
    }
}

extern "C" void kernel_launch(void* const* d_in, const int* in_sizes, int n_in,
                              void* d_out, int out_size) {
    const float* s      = (const float*)d_in[0];
    const float* v      = (const float*)d_in[1];
    const float* radial = (const float*)d_in[2];
    const float* f_cut  = (const float*)d_in[3];
    const float* uvec   = (const float*)d_in[4];
    const int*   eidx   = (const int*)d_in[5];
    const float* W1     = (const float*)d_in[6];
    const float* b1     = (const float*)d_in[7];
    const float* W2     = (const float*)d_in[8];
    const float* b2     = (const float*)d_in[9];
    const float* Wr     = (const float*)d_in[10];
    const float* br     = (const float*)d_in[11];
    float* out = (float*)d_out;

    k_node<<<GRID_NODE, 256>>>(s, v, W1, b1, W2, b2, out);
    k_edge<<<GRID_EDGE, 256>>>(v, radial, f_cut, uvec, eidx, Wr, br, out);
}

// round 15
// speedup vs baseline: 1.0056x; 1.0056x over previous
#include <cuda_runtime.h>
#include <math.h>
#include <stdint.h>

#define N_NODES 50000
#define N_EDGES 800000
#define NF 64
#define TILE_E 64
#define N_TILES (N_EDGES / TILE_E)   // 12500 edge tiles
#define N_NTILES (N_NODES / 16)      // 3125 node tiles
#define GRID_NODE 296                // 2 CTAs/SM resident (smem ~76KB)
#define GRID_EDGE 296                // 2 CTAs/SM (smem ~98KB)

#define SWR_STRIDE 200               // 32 x 200 tf32 bits (bank conflict-free)
#define SRAD_STRIDE 36               // 64 x 36 raw fp32 (16B-aligned rows, cf-free)
#define SW_STRIDE 200                // 64 x 200 f32 W tile
#define SW2_STRIDE 200               // 64 x 200 tf32 W2
#define SH_STRIDE 68                 // 16 x 68 tf32 h

__device__ __align__(16) float g_phi[N_NODES * 3 * NF];    // 38.4 MB

__device__ __forceinline__ uint32_t f2tf32(float f) {
    uint32_t r;
    asm("cvt.rna.tf32.f32 %0, %1;" : "=r"(r) : "f"(f));
    return r;
}

__device__ __forceinline__ void mma_tf32(float c[4], const uint32_t a[4],
                                         uint32_t b0, uint32_t b1) {
    asm("mma.sync.aligned.m16n8k8.row.col.f32.tf32.tf32.f32 "
        "{%0,%1,%2,%3}, {%4,%5,%6,%7}, {%8,%9}, {%0,%1,%2,%3};"
        : "+f"(c[0]), "+f"(c[1]), "+f"(c[2]), "+f"(c[3])
        : "r"(a[0]), "r"(a[1]), "r"(a[2]), "r"(a[3]), "r"(b0), "r"(b1));
}

__device__ __forceinline__ void red_add_v4(float* p, float a, float b, float c, float d) {
    asm volatile("red.global.add.v4.f32 [%0], {%1, %2, %3, %4};"
                 :: "l"(p), "f"(a), "f"(b), "f"(c), "f"(d));
}

__device__ __forceinline__ void cp_async16(void* smem, const void* gmem) {
    uint32_t sa = (uint32_t)__cvta_generic_to_shared(smem);
    asm volatile("cp.async.cg.shared.global [%0], [%1], 16;" :: "r"(sa), "l"(gmem));
}
#define CP_COMMIT() asm volatile("cp.async.commit_group;" ::: "memory")
#define CP_WAIT1()  asm volatile("cp.async.wait_group 1;" ::: "memory")

// ---------- Persistent node kernel: out=[s|v] copy + phi MLP (tf32 mma) ----------
__global__ void __launch_bounds__(256) k_node(
    const float* __restrict__ s, const float* __restrict__ v,
    const float* __restrict__ W1, const float* __restrict__ b1,
    const float* __restrict__ W2, const float* __restrict__ b2,
    float* __restrict__ out) {
    __shared__ float sW1[NF * NF];            // 16 KB
    __shared__ uint32_t sW2T[NF * SW2_STRIDE]; // 51.2 KB tf32
    __shared__ float sS[16 * NF];             // 4 KB
    __shared__ uint32_t sHT[16 * SH_STRIDE];  // 4.35 KB tf32

    int tid = threadIdx.x;

    // out = [s | v] (grid-stride; overlaps weight staging + MLP)
    {
        const int NS4 = N_NODES * NF / 4;
        const int NV4 = N_NODES * 3 * NF / 4;
        const float4* s4 = (const float4*)s;
        const float4* v4 = (const float4*)v;
        float4* out4 = (float4*)out;
        for (int i = blockIdx.x * 256 + tid; i < NS4 + NV4; i += GRID_NODE * 256) {
            if (i < NS4) out4[i] = s4[i];
            else out4[i] = v4[i - NS4];
        }
    }

    for (int i = tid; i < NF * NF; i += 256) sW1[i] = W1[i];
    for (int i = tid; i < NF * 192; i += 256) {
        int k = i / 192, n = i % 192;
        sW2T[k * SW2_STRIDE + n] = f2tf32(W2[i]);
    }

    int c = tid & 63;
    int q = tid >> 6;
    float bb1 = b1[c];

    // phase-2 mma mapping: 8 warps x n24 each (3 n-tiles), m16, k64 (8 ksteps)
    int wid = tid >> 5, lane = tid & 31;
    int kc = lane & 3;
    int mr = lane >> 2;
    float2 bias[3];
#pragma unroll
    for (int nt = 0; nt < 3; nt++)
        bias[nt] = *(const float2*)&b2[wid * 24 + nt * 8 + (lane & 3) * 2];

    for (int tile = blockIdx.x; tile < N_NTILES; tile += GRID_NODE) {
        int node0 = tile * 16;
        __syncthreads();
        for (int i = tid; i < 16 * NF; i += 256) sS[i] = s[node0 * NF + i];
        __syncthreads();

        // Phase 1: h = silu(s @ W1 + b1) -> sHT (tf32 bits)
        {
            float a0 = bb1, a1 = bb1, a2 = bb1, a3 = bb1;
            const float* sr = &sS[q * 4 * NF];
#pragma unroll 8
            for (int k = 0; k < NF; k++) {
                float w = sW1[k * NF + c];
                a0 += sr[k] * w;
                a1 += sr[NF + k] * w;
                a2 += sr[2 * NF + k] * w;
                a3 += sr[3 * NF + k] * w;
            }
            int o = q * 4;
            sHT[o * SH_STRIDE + c]       = f2tf32(a0 / (1.f + expf(-a0)));
            sHT[(o + 1) * SH_STRIDE + c] = f2tf32(a1 / (1.f + expf(-a1)));
            sHT[(o + 2) * SH_STRIDE + c] = f2tf32(a2 / (1.f + expf(-a2)));
            sHT[(o + 3) * SH_STRIDE + c] = f2tf32(a3 / (1.f + expf(-a3)));
        }
        __syncthreads();

        // Phase 2: phi = h @ W2 + b2 via tf32 mma (m16 x n24 per warp)
        float C[3][4];
#pragma unroll
        for (int nt = 0; nt < 3; nt++) {
            C[nt][0] = bias[nt].x; C[nt][1] = bias[nt].y;
            C[nt][2] = bias[nt].x; C[nt][3] = bias[nt].y;
        }
#pragma unroll
        for (int ks = 0; ks < 8; ks++) {
            uint32_t a[4];
            int col = ks * 8 + kc;
            a[0] = sHT[mr * SH_STRIDE + col];
            a[1] = sHT[(mr + 8) * SH_STRIDE + col];
            a[2] = sHT[mr * SH_STRIDE + col + 4];
            a[3] = sHT[(mr + 8) * SH_STRIDE + col + 4];
#pragma unroll
            for (int nt = 0; nt < 3; nt++) {
                int ncol = wid * 24 + nt * 8 + mr;
                uint32_t b0 = sW2T[(ks * 8 + kc) * SW2_STRIDE + ncol];
                uint32_t b1 = sW2T[(ks * 8 + kc + 4) * SW2_STRIDE + ncol];
                mma_tf32(C[nt], a, b0, b1);
            }
        }
#pragma unroll
        for (int nt = 0; nt < 3; nt++) {
            int col = wid * 24 + nt * 8 + (lane & 3) * 2;
            *(float2*)&g_phi[(node0 + mr) * 192 + col] = make_float2(C[nt][0], C[nt][1]);
            *(float2*)&g_phi[(node0 + mr + 8) * 192 + col] = make_float2(C[nt][2], C[nt][3]);
        }
    }
}

// ---------- Persistent edge kernel: cp.async double-buffered tiles ----------
__global__ void __launch_bounds__(256) k_edge(
    const float* __restrict__ v, const float* __restrict__ radial,
    const float* __restrict__ f_cut, const float* __restrict__ uvec,
    const int* __restrict__ eidx, const float* __restrict__ Wr,
    const float* __restrict__ br, float* __restrict__ out) {
    __shared__ uint32_t sWrT[32 * SWR_STRIDE];                       // 25.6 KB
    __shared__ __align__(16) float sRad[2][TILE_E * SRAD_STRIDE];    // 2 x 9.2 KB
    __shared__ __align__(16) float sW[TILE_E * SW_STRIDE];           // 51.2 KB
    __shared__ __align__(16) int sIJ[2][2 * TILE_E];                 // 2 x 512 B
    __shared__ __align__(16) float sFc[2][TILE_E];                   // 2 x 256 B
    __shared__ __align__(16) float sU[2][TILE_E * 3];                // 2 x 768 B

    int tid = threadIdx.x;

    for (int i = tid; i < 32 * 192; i += 256) {
        int r = i / 192, c = i % 192;
        sWrT[r * SWR_STRIDE + c] = f2tf32(Wr[i]);
    }

    // GEMM mapping: 8 warps = 4 m-tiles x 2 n-halves (m16 x n96 each)
    int wid = tid >> 5, lane = tid & 31;
    int mt = wid & 3;
    int nh = wid >> 2;
    int rlo = mt * 16 + (lane >> 2);
    int kc = lane & 3;
    int nb = nh * 96 + (lane >> 2);

    // Epilogue mapping
    int g = tid & 15;
    int eq = tid >> 4;
    float4 Bs = *(const float4*)&br[4 * g];
    float4 Bv = *(const float4*)&br[NF + 4 * g];
    float4 Bx = *(const float4*)&br[2 * NF + 4 * g];

    // tile-fill via cp.async: rad (512 x 16B) + meta (96 x 16B)
    auto issue_tile = [&](int t, int b) {
        // rad: 64 rows x 128B; thread handles 2 chunks
        for (int i = tid; i < 512; i += 256) {
            int e = i >> 3, c = i & 7;
            cp_async16(&sRad[b][e * SRAD_STRIDE + c * 4],
                       radial + (size_t)t * TILE_E * 32 + e * 32 + c * 4);
        }
        if (tid < 16)
            cp_async16(&sIJ[b][tid * 4], eidx + t * TILE_E + tid * 4);
        else if (tid < 32)
            cp_async16(&sIJ[b][64 + (tid - 16) * 4],
                       eidx + N_EDGES + t * TILE_E + (tid - 16) * 4);
        else if (tid < 48)
            cp_async16(&sFc[b][(tid - 32) * 4], f_cut + t * TILE_E + (tid - 32) * 4);
        else if (tid < 96)
            cp_async16(&sU[b][(tid - 48) * 4],
                       uvec + (size_t)t * TILE_E * 3 + (tid - 48) * 4);
    };

    int cb = 0;
    issue_tile(blockIdx.x, 0);
    CP_COMMIT();

    for (int tile = blockIdx.x; tile < N_TILES; tile += GRID_EDGE) {
        int tn = tile + GRID_EDGE;
        if (tn >= N_TILES) tn = tile;          // clamped dummy prefetch (uniform groups)
        issue_tile(tn, cb ^ 1);
        CP_COMMIT();
        CP_WAIT1();                             // buf[cb] complete
        __syncthreads();                        // publish buf[cb]

        // ---- tf32 GEMM: W' = rad @ Wr  (64x32 @ 32x192) ----
        uint32_t a[4][4];
#pragma unroll
        for (int ks = 0; ks < 4; ks++) {
            int col = ks * 8 + kc;
            a[ks][0] = f2tf32(sRad[cb][rlo * SRAD_STRIDE + col]);
            a[ks][1] = f2tf32(sRad[cb][(rlo + 8) * SRAD_STRIDE + col]);
            a[ks][2] = f2tf32(sRad[cb][rlo * SRAD_STRIDE + col + 4]);
            a[ks][3] = f2tf32(sRad[cb][(rlo + 8) * SRAD_STRIDE + col + 4]);
        }

        float c[12][4];
#pragma unroll
        for (int nt = 0; nt < 12; nt++) {
            c[nt][0] = 0.f; c[nt][1] = 0.f; c[nt][2] = 0.f; c[nt][3] = 0.f;
            int ncol = nb + nt * 8;
#pragma unroll
            for (int ks = 0; ks < 4; ks++) {
                uint32_t b0 = sWrT[(ks * 8 + kc) * SWR_STRIDE + ncol];
                uint32_t b1 = sWrT[(ks * 8 + kc + 4) * SWR_STRIDE + ncol];
                mma_tf32(c[nt], a[ks], b0, b1);
            }
        }

#pragma unroll
        for (int nt = 0; nt < 12; nt++) {
            int col = nh * 96 + nt * 8 + (lane & 3) * 2;
            *(float2*)&sW[rlo * SW_STRIDE + col] = make_float2(c[nt][0], c[nt][1]);
            *(float2*)&sW[(rlo + 8) * SW_STRIDE + col] = make_float2(c[nt][2], c[nt][3]);
        }
        __syncthreads();

        // ---- epilogue: 2-edge prefetch batches (R11 structure) ----
        const int* sIc = sIJ[cb];
        const int* sJc = sIJ[cb] + 64;
        const float* sFcc = sFc[cb];
        const float* sUc = sU[cb];
#pragma unroll
        for (int half = 0; half < 2; half++) {
            int elA = eq * 4 + half * 2;
            int elB = elA + 1;
            int iA = sIc[elA], jA = sJc[elA];
            int iB = sIc[elB], jB = sJc[elB];
            float fcA = sFcc[elA], fcB = sFcc[elB];

            const float4* pjA = (const float4*)&g_phi[jA * 192 + 4 * g];
            const float4* vjA = (const float4*)&v[(size_t)jA * 192 + 4 * g];
            const float4* pjB = (const float4*)&g_phi[jB * 192 + 4 * g];
            const float4* vjB = (const float4*)&v[(size_t)jB * 192 + 4 * g];
            float4 psA = pjA[0], pvA = pjA[16], pxA = pjA[32];
            float4 vdA0 = vjA[0], vdA1 = vjA[16], vdA2 = vjA[32];
            float4 psB = pjB[0], pvB = pjB[16], pxB = pjB[32];
            float4 vdB0 = vjB[0], vdB1 = vjB[16], vdB2 = vjB[32];

            {
                const float* wrow = &sW[elA * SW_STRIDE + 4 * g];
                float4 wsv = *(const float4*)wrow;
                float4 wvv = *(const float4*)(wrow + 64);
                float4 wxv = *(const float4*)(wrow + 128);

                float xs0 = psA.x * ((wsv.x + Bs.x) * fcA), xs1 = psA.y * ((wsv.y + Bs.y) * fcA);
                float xs2 = psA.z * ((wsv.z + Bs.z) * fcA), xs3 = psA.w * ((wsv.w + Bs.w) * fcA);
                red_add_v4(out + iA * NF + 4 * g, xs0, xs1, xs2, xs3);

                float xvv0 = pvA.x * ((wvv.x + Bv.x) * fcA), xvv1 = pvA.y * ((wvv.y + Bv.y) * fcA);
                float xvv2 = pvA.z * ((wvv.z + Bv.z) * fcA), xvv3 = pvA.w * ((wvv.w + Bv.w) * fcA);
                float xvs0 = pxA.x * ((wxv.x + Bx.x) * fcA), xvs1 = pxA.y * ((wxv.y + Bx.y) * fcA);
                float xvs2 = pxA.z * ((wxv.z + Bx.z) * fcA), xvs3 = pxA.w * ((wxv.w + Bx.w) * fcA);

                float u0 = sUc[elA * 3 + 0], u1 = sUc[elA * 3 + 1], u2 = sUc[elA * 3 + 2];
                float* ov = out + N_NODES * NF + iA * 192 + 4 * g;
                red_add_v4(ov,
                           vdA0.x * xvv0 + xvs0 * u0, vdA0.y * xvv1 + xvs1 * u0,
                           vdA0.z * xvv2 + xvs2 * u0, vdA0.w * xvv3 + xvs3 * u0);
                red_add_v4(ov + 64,
                           vdA1.x * xvv0 + xvs0 * u1, vdA1.y * xvv1 + xvs1 * u1,
                           vdA1.z * xvv2 + xvs2 * u1, vdA1.w * xvv3 + xvs3 * u1);
                red_add_v4(ov + 128,
                           vdA2.x * xvv0 + xvs0 * u2, vdA2.y * xvv1 + xvs1 * u2,
                           vdA2.z * xvv2 + xvs2 * u2, vdA2.w * xvv3 + xvs3 * u2);
            }
            {
                const float* wrow = &sW[elB * SW_STRIDE + 4 * g];
                float4 wsv = *(const float4*)wrow;
                float4 wvv = *(const float4*)(wrow + 64);
                float4 wxv = *(const float4*)(wrow + 128);

                float xs0 = psB.x * ((wsv.x + Bs.x) * fcB), xs1 = psB.y * ((wsv.y + Bs.y) * fcB);
                float xs2 = psB.z * ((wsv.z + Bs.z) * fcB), xs3 = psB.w * ((wsv.w + Bs.w) * fcB);
                red_add_v4(out + iB * NF + 4 * g, xs0, xs1, xs2, xs3);

                float xvv0 = pvB.x * ((wvv.x + Bv.x) * fcB), xvv1 = pvB.y * ((wvv.y + Bv.y) * fcB);
                float xvv2 = pvB.z * ((wvv.z + Bv.z) * fcB), xvv3 = pvB.w * ((wvv.w + Bv.w) * fcB);
                float xvs0 = pxB.x * ((wxv.x + Bx.x) * fcB), xvs1 = pxB.y * ((wxv.y + Bx.y) * fcB);
                float xvs2 = pxB.z * ((wxv.z + Bx.z) * fcB), xvs3 = pxB.w * ((wxv.w + Bx.w) * fcB);

                float u0 = sUc[elB * 3 + 0], u1 = sUc[elB * 3 + 1], u2 = sUc[elB * 3 + 2];
                float* ov = out + N_NODES * NF + iB * 192 + 4 * g;
                red_add_v4(ov,
                           vdB0.x * xvv0 + xvs0 * u0, vdB0.y * xvv1 + xvs1 * u0,
                           vdB0.z * xvv2 + xvs2 * u0, vdB0.w * xvv3 + xvs3 * u0);
                red_add_v4(ov + 64,
                           vdB1.x * xvv0 + xvs0 * u1, vdB1.y * xvv1 + xvs1 * u1,
                           vdB1.z * xvv2 + xvs2 * u1, vdB1.w * xvv3 + xvs3 * u1);
                red_add_v4(ov + 128,
                           vdB2.x * xvv0 + xvs0 * u2, vdB2.y * xvv1 + xvs1 * u2,
                           vdB2.z * xvv2 + xvs2 * u2, vdB2.w * xvv3 + xvs3 * u2);
            }
        }
        __syncthreads();   // all reads of buf[cb] + sW done before next overwrite
        cb ^= 1;
    }
}

extern "C" void kernel_launch(void* const* d_in, const int* in_sizes, int n_in,
                              void* d_out, int out_size) {
    const float* s      = (const float*)d_in[0];
    const float* v      = (const float*)d_in[1];
    const float* radial = (const float*)d_in[2];
    const float* f_cut  = (const float*)d_in[3];
    const float* uvec   = (const float*)d_in[4];
    const int*   eidx   = (const int*)d_in[5];
    const float* W1     = (const float*)d_in[6];
    const float* b1     = (const float*)d_in[7];
    const float* W2     = (const float*)d_in[8];
    const float* b2     = (const float*)d_in[9];
    const float* Wr     = (const float*)d_in[10];
    const float* br     = (const float*)d_in[11];
    float* out = (float*)d_out;

    k_node<<<GRID_NODE, 256>>>(s, v, W1, b1, W2, b2, out);
    k_edge<<<GRID_EDGE, 256>>>(v, radial, f_cut, uvec, eidx, Wr, br, out);
}